// round 1
// baseline (speedup 1.0000x reference)
#include <cuda_runtime.h>

// ---------------------------------------------------------------------------
// T5RelativeAttention  (B=32, N=577, DIM=768, H=12, Dh=64)
// Round 1: fp32 SIMT baseline.
//   K0: build padded bias table  bias[h][i][j]  (12 x 640 x 640, zero padded)
//   K1: QKV GEMM  -> g_q (x0.125), g_k, g_v  in [b][h][n][d] layout
//   K2: fused attention (flash-style online softmax), 64-query x 64-key tiles
//   K3: output projection GEMM + bias -> d_out
// ---------------------------------------------------------------------------

constexpr int B_   = 32;
constexpr int H_   = 12;
constexpr int N_   = 577;
constexpr int NP_  = 576;
constexpr int D_   = 768;
constexpr int DH_  = 64;
constexpr int NRELC = 2209;
constexpr int BPAD = 640;                 // padded bias width/height
constexpr int MR   = B_ * N_;             // 18464 rows

#define CDIV(a,b) (((a)+(b)-1)/(b))

__device__ float g_q[(size_t)B_*H_*N_*DH_];
__device__ float g_k[(size_t)B_*H_*N_*DH_];
__device__ float g_v[(size_t)B_*H_*N_*DH_];
__device__ float g_bias[(size_t)H_*BPAD*BPAD];
__device__ float g_ao[(size_t)MR*D_];

// ---------------------------------------------------------------------------
// K0: bias table.  bias[h][i][j]:
//   i==576          -> beta1[h][j]
//   i<576, j==0     -> beta2[h][i]
//   i<576, j>=1     -> beta3[h][ map[i][j-1] ]
// padded region (i>=577 or j>=577) -> 0
// ---------------------------------------------------------------------------
__global__ void bias_build(const float* __restrict__ b1, const float* __restrict__ b2,
                           const float* __restrict__ b3, const int* __restrict__ map) {
    int idx = blockIdx.x * blockDim.x + threadIdx.x;
    constexpr int TOT = H_ * BPAD * BPAD;
    if (idx >= TOT) return;
    int h = idx / (BPAD * BPAD);
    int r = idx - h * (BPAD * BPAD);
    int i = r / BPAD;
    int j = r - i * BPAD;
    float v = 0.f;
    if (i < N_ && j < N_) {
        if (i == NP_)      v = b1[h * N_ + j];
        else if (j == 0)   v = b2[h * NP_ + i];
        else               v = b3[h * NRELC + map[i * NP_ + (j - 1)]];
    }
    g_bias[idx] = v;
}

// ---------------------------------------------------------------------------
// K1: QKV GEMM.  C[m][c] = dot(x[m,:], qkv_w[c,:]),  m in [0,18464), c in [0,2304)
// Tile 64x64, BK=16, 256 threads, 4x4 per thread. Epilogue scatters to q/k/v.
// ---------------------------------------------------------------------------
__global__ void __launch_bounds__(256) gemm_qkv(const float* __restrict__ A,
                                                const float* __restrict__ W) {
    __shared__ float As[16][65];
    __shared__ float Bs[16][65];
    const int m0 = blockIdx.y * 64;
    const int c0 = blockIdx.x * 64;
    const int t  = threadIdx.x;
    const int ty4 = (t >> 4) * 4;
    const int tx4 = (t & 15) * 4;
    const int lr = t >> 2;            // 0..63
    const int lc = (t & 3) * 4;       // 0,4,8,12
    const bool aval = (m0 + lr) < MR;
    const float* Ap = A + (size_t)(m0 + lr) * D_ + lc;
    const float* Wp = W + (size_t)(c0 + lr) * D_ + lc;

    float acc[4][4] = {};
    for (int k0 = 0; k0 < D_; k0 += 16) {
        float4 av = aval ? *(const float4*)(Ap + k0) : make_float4(0.f,0.f,0.f,0.f);
        float4 bv = *(const float4*)(Wp + k0);
        __syncthreads();
        As[lc+0][lr] = av.x; As[lc+1][lr] = av.y; As[lc+2][lr] = av.z; As[lc+3][lr] = av.w;
        Bs[lc+0][lr] = bv.x; Bs[lc+1][lr] = bv.y; Bs[lc+2][lr] = bv.z; Bs[lc+3][lr] = bv.w;
        __syncthreads();
        #pragma unroll
        for (int kk = 0; kk < 16; kk++) {
            float a0 = As[kk][ty4+0], a1 = As[kk][ty4+1], a2 = As[kk][ty4+2], a3 = As[kk][ty4+3];
            float b0 = Bs[kk][tx4+0], b1 = Bs[kk][tx4+1], b2 = Bs[kk][tx4+2], b3 = Bs[kk][tx4+3];
            acc[0][0] += a0*b0; acc[0][1] += a0*b1; acc[0][2] += a0*b2; acc[0][3] += a0*b3;
            acc[1][0] += a1*b0; acc[1][1] += a1*b1; acc[1][2] += a1*b2; acc[1][3] += a1*b3;
            acc[2][0] += a2*b0; acc[2][1] += a2*b1; acc[2][2] += a2*b2; acc[2][3] += a2*b3;
            acc[3][0] += a3*b0; acc[3][1] += a3*b1; acc[3][2] += a3*b2; acc[3][3] += a3*b3;
        }
    }
    // epilogue: c = s*768 + h*64 + d ; whole 64-wide tile shares (s,h)
    const int s = c0 / D_;
    const int h = (c0 % D_) / DH_;
    const float scl = (s == 0) ? 0.125f : 1.0f;   // fold 1/sqrt(64) into Q
    float* dst = (s == 0) ? g_q : (s == 1) ? g_k : g_v;
    #pragma unroll
    for (int a = 0; a < 4; a++) {
        int m = m0 + ty4 + a;
        if (m >= MR) break;
        int bb = m / N_;
        int n  = m - bb * N_;
        size_t off = (((size_t)(bb * H_ + h)) * N_ + n) * DH_ + tx4;
        *(float4*)(dst + off) = make_float4(acc[a][0]*scl, acc[a][1]*scl,
                                            acc[a][2]*scl, acc[a][3]*scl);
    }
}

// ---------------------------------------------------------------------------
// K2: fused attention. Block = (qtile of 64, bh). 256 threads, 4x4 register
// tiles for both S=QK^T and O=PV. Online softmax, row stats via 16-lane shfl.
// Dynamic shared: Qs[d][i], Ks[d][j], Vs[j][d], Ps[j][i], each 64x65 floats.
// ---------------------------------------------------------------------------
__global__ void __launch_bounds__(256) attn_kernel() {
    extern __shared__ float sh[];
    float* Qs = sh;
    float* Ks = sh + 64*65;
    float* Vs = sh + 2*64*65;
    float* Ps = sh + 3*64*65;

    const int bh = blockIdx.y;
    const int h  = bh % H_;
    const int i0 = blockIdx.x * 64;
    const int t  = threadIdx.x;
    const int ty4 = (t >> 4) * 4;
    const int tx4 = (t & 15) * 4;

    const size_t base = (size_t)bh * N_ * DH_;
    const float* qb = g_q + base;
    const float* kb = g_k + base;
    const float* vb = g_v + base;

    // load Q tile transposed -> Qs[d][i]
    {
        const int rbase = (t >> 4);
        const int c4 = (t & 15) * 4;
        #pragma unroll
        for (int rr = 0; rr < 4; rr++) {
            int r = rr * 16 + rbase;
            int gi = i0 + r;
            float4 v = (gi < N_) ? *(const float4*)(qb + (size_t)gi * DH_ + c4)
                                 : make_float4(0.f,0.f,0.f,0.f);
            Qs[(c4+0)*65 + r] = v.x;
            Qs[(c4+1)*65 + r] = v.y;
            Qs[(c4+2)*65 + r] = v.z;
            Qs[(c4+3)*65 + r] = v.w;
        }
    }

    float m_[4], l_[4], o[4][4];
    #pragma unroll
    for (int a = 0; a < 4; a++) {
        m_[a] = -1e30f; l_[a] = 0.f;
        #pragma unroll
        for (int b = 0; b < 4; b++) o[a][b] = 0.f;
    }

    const float* brow = g_bias + ((size_t)h * BPAD + i0 + ty4) * BPAD + tx4;

    for (int kt = 0; kt < 10; kt++) {
        const int j0 = kt * 64;
        __syncthreads();   // previous iter's Ps/Vs/Ks readers done
        // load K tile transposed -> Ks[d][j]; V tile natural -> Vs[j][d]
        {
            const int rbase = (t >> 4);
            const int c4 = (t & 15) * 4;
            #pragma unroll
            for (int rr = 0; rr < 4; rr++) {
                int r = rr * 16 + rbase;
                int gj = j0 + r;
                float4 kv = (gj < N_) ? *(const float4*)(kb + (size_t)gj * DH_ + c4)
                                      : make_float4(0.f,0.f,0.f,0.f);
                Ks[(c4+0)*65 + r] = kv.x;
                Ks[(c4+1)*65 + r] = kv.y;
                Ks[(c4+2)*65 + r] = kv.z;
                Ks[(c4+3)*65 + r] = kv.w;
                float4 vv = (gj < N_) ? *(const float4*)(vb + (size_t)gj * DH_ + c4)
                                      : make_float4(0.f,0.f,0.f,0.f);
                Vs[r*65 + c4+0] = vv.x;
                Vs[r*65 + c4+1] = vv.y;
                Vs[r*65 + c4+2] = vv.z;
                Vs[r*65 + c4+3] = vv.w;
            }
        }
        __syncthreads();

        // S = Q K^T  (4x4 per thread)
        float s[4][4];
        #pragma unroll
        for (int a = 0; a < 4; a++)
            #pragma unroll
            for (int b = 0; b < 4; b++) s[a][b] = 0.f;

        #pragma unroll 8
        for (int d = 0; d < 64; d++) {
            float q0 = Qs[d*65 + ty4+0], q1 = Qs[d*65 + ty4+1];
            float q2 = Qs[d*65 + ty4+2], q3 = Qs[d*65 + ty4+3];
            float k0 = Ks[d*65 + tx4+0], k1 = Ks[d*65 + tx4+1];
            float k2 = Ks[d*65 + tx4+2], k3 = Ks[d*65 + tx4+3];
            s[0][0] += q0*k0; s[0][1] += q0*k1; s[0][2] += q0*k2; s[0][3] += q0*k3;
            s[1][0] += q1*k0; s[1][1] += q1*k1; s[1][2] += q1*k2; s[1][3] += q1*k3;
            s[2][0] += q2*k0; s[2][1] += q2*k1; s[2][2] += q2*k2; s[2][3] += q2*k3;
            s[3][0] += q3*k0; s[3][1] += q3*k1; s[3][2] += q3*k2; s[3][3] += q3*k3;
        }

        // + bias (padded table, always in-bounds, float4)
        #pragma unroll
        for (int a = 0; a < 4; a++) {
            float4 bv = *(const float4*)(brow + (size_t)a * BPAD + j0);
            s[a][0] += bv.x; s[a][1] += bv.y; s[a][2] += bv.z; s[a][3] += bv.w;
        }
        // mask out-of-range keys
        #pragma unroll
        for (int b = 0; b < 4; b++) {
            if (j0 + tx4 + b >= N_) {
                s[0][b] = -1e30f; s[1][b] = -1e30f; s[2][b] = -1e30f; s[3][b] = -1e30f;
            }
        }

        // online softmax update, per query row (16 lanes own a row)
        #pragma unroll
        for (int a = 0; a < 4; a++) {
            float mx = fmaxf(fmaxf(s[a][0], s[a][1]), fmaxf(s[a][2], s[a][3]));
            #pragma unroll
            for (int off = 8; off; off >>= 1)
                mx = fmaxf(mx, __shfl_xor_sync(0xffffffffu, mx, off));
            float mn = fmaxf(m_[a], mx);
            float corr = __expf(m_[a] - mn);
            float rs = 0.f;
            #pragma unroll
            for (int b = 0; b < 4; b++) {
                float p = __expf(s[a][b] - mn);
                s[a][b] = p;
                rs += p;
            }
            #pragma unroll
            for (int off = 8; off; off >>= 1)
                rs += __shfl_xor_sync(0xffffffffu, rs, off);
            l_[a] = l_[a] * corr + rs;
            m_[a] = mn;
            #pragma unroll
            for (int b = 0; b < 4; b++) o[a][b] *= corr;
        }

        // stage P transposed -> Ps[j][i]
        #pragma unroll
        for (int b = 0; b < 4; b++)
            #pragma unroll
            for (int a = 0; a < 4; a++)
                Ps[(tx4+b)*65 + ty4 + a] = s[a][b];
        __syncthreads();

        // O += P V
        #pragma unroll 8
        for (int j = 0; j < 64; j++) {
            float p0 = Ps[j*65 + ty4+0], p1 = Ps[j*65 + ty4+1];
            float p2 = Ps[j*65 + ty4+2], p3 = Ps[j*65 + ty4+3];
            float v0 = Vs[j*65 + tx4+0], v1 = Vs[j*65 + tx4+1];
            float v2 = Vs[j*65 + tx4+2], v3 = Vs[j*65 + tx4+3];
            o[0][0] += p0*v0; o[0][1] += p0*v1; o[0][2] += p0*v2; o[0][3] += p0*v3;
            o[1][0] += p1*v0; o[1][1] += p1*v1; o[1][2] += p1*v2; o[1][3] += p1*v3;
            o[2][0] += p2*v0; o[2][1] += p2*v1; o[2][2] += p2*v2; o[2][3] += p2*v3;
            o[3][0] += p3*v0; o[3][1] += p3*v1; o[3][2] += p3*v2; o[3][3] += p3*v3;
        }
    }

    // epilogue: normalize + store to [b][n][h*64+d]
    const int b = bh / H_;
    #pragma unroll
    for (int a = 0; a < 4; a++) {
        int gi = i0 + ty4 + a;
        if (gi >= N_) continue;
        float inv = 1.f / l_[a];
        size_t off = ((size_t)b * N_ + gi) * D_ + h * DH_ + tx4;
        *(float4*)(g_ao + off) = make_float4(o[a][0]*inv, o[a][1]*inv,
                                             o[a][2]*inv, o[a][3]*inv);
    }
}

// ---------------------------------------------------------------------------
// K3: output projection.  out[m][c] = dot(g_ao[m,:], proj_w[c,:]) + proj_b[c]
// ---------------------------------------------------------------------------
__global__ void __launch_bounds__(256) gemm_proj(const float* __restrict__ W,
                                                 const float* __restrict__ pbias,
                                                 float* __restrict__ out) {
    __shared__ float As[16][65];
    __shared__ float Bs[16][65];
    const int m0 = blockIdx.y * 64;
    const int c0 = blockIdx.x * 64;
    const int t  = threadIdx.x;
    const int ty4 = (t >> 4) * 4;
    const int tx4 = (t & 15) * 4;
    const int lr = t >> 2;
    const int lc = (t & 3) * 4;
    const bool aval = (m0 + lr) < MR;
    const float* Ap = g_ao + (size_t)(m0 + lr) * D_ + lc;
    const float* Wp = W + (size_t)(c0 + lr) * D_ + lc;

    float acc[4][4] = {};
    for (int k0 = 0; k0 < D_; k0 += 16) {
        float4 av = aval ? *(const float4*)(Ap + k0) : make_float4(0.f,0.f,0.f,0.f);
        float4 bv = *(const float4*)(Wp + k0);
        __syncthreads();
        As[lc+0][lr] = av.x; As[lc+1][lr] = av.y; As[lc+2][lr] = av.z; As[lc+3][lr] = av.w;
        Bs[lc+0][lr] = bv.x; Bs[lc+1][lr] = bv.y; Bs[lc+2][lr] = bv.z; Bs[lc+3][lr] = bv.w;
        __syncthreads();
        #pragma unroll
        for (int kk = 0; kk < 16; kk++) {
            float a0 = As[kk][ty4+0], a1 = As[kk][ty4+1], a2 = As[kk][ty4+2], a3 = As[kk][ty4+3];
            float b0 = Bs[kk][tx4+0], b1 = Bs[kk][tx4+1], b2 = Bs[kk][tx4+2], b3 = Bs[kk][tx4+3];
            acc[0][0] += a0*b0; acc[0][1] += a0*b1; acc[0][2] += a0*b2; acc[0][3] += a0*b3;
            acc[1][0] += a1*b0; acc[1][1] += a1*b1; acc[1][2] += a1*b2; acc[1][3] += a1*b3;
            acc[2][0] += a2*b0; acc[2][1] += a2*b1; acc[2][2] += a2*b2; acc[2][3] += a2*b3;
            acc[3][0] += a3*b0; acc[3][1] += a3*b1; acc[3][2] += a3*b2; acc[3][3] += a3*b3;
        }
    }
    float4 bv4 = *(const float4*)(pbias + c0 + tx4);
    #pragma unroll
    for (int a = 0; a < 4; a++) {
        int m = m0 + ty4 + a;
        if (m >= MR) break;
        *(float4*)(out + (size_t)m * D_ + c0 + tx4) =
            make_float4(acc[a][0]+bv4.x, acc[a][1]+bv4.y, acc[a][2]+bv4.z, acc[a][3]+bv4.w);
    }
}

// ---------------------------------------------------------------------------
extern "C" void kernel_launch(void* const* d_in, const int* in_sizes, int n_in,
                              void* d_out, int out_size) {
    (void)in_sizes; (void)n_in; (void)out_size;
    const float* x    = (const float*)d_in[0];
    const float* qkvw = (const float*)d_in[1];
    const float* pw   = (const float*)d_in[2];
    const float* pb   = (const float*)d_in[3];
    const float* b1   = (const float*)d_in[4];
    const float* b2   = (const float*)d_in[5];
    const float* b3   = (const float*)d_in[6];
    const int*   map  = (const int*)d_in[7];
    float* out = (float*)d_out;

    const int attn_smem = 4 * 64 * 65 * (int)sizeof(float);   // 66,560 B
    cudaFuncSetAttribute(attn_kernel, cudaFuncAttributeMaxDynamicSharedMemorySize, attn_smem);

    bias_build<<<CDIV(H_ * BPAD * BPAD, 256), 256>>>(b1, b2, b3, map);
    gemm_qkv<<<dim3(2304 / 64, CDIV(MR, 64)), 256>>>(x, qkvw);
    attn_kernel<<<dim3(CDIV(N_, 64), B_ * H_), 256, attn_smem>>>();
    gemm_proj<<<dim3(D_ / 64, CDIV(MR, 64)), 256>>>(pw, pb, out);
}

// round 3
// speedup vs baseline: 1.5322x; 1.5322x over previous
#include <cuda_runtime.h>

// ---------------------------------------------------------------------------
// T5RelativeAttention  (B=32, N=577, DIM=768, H=12, Dh=64)
// Round 3: round-2 design (fma.rn.f32x2 + 128x128 tiles, 8x8 microtile) with
// the host-side __device__-symbol-as-argument bug fixed: proj GEMM reads g_ao
// from device code, not via a host-passed pointer.
// ---------------------------------------------------------------------------

using u64 = unsigned long long;

constexpr int B_   = 32;
constexpr int H_   = 12;
constexpr int N_   = 577;
constexpr int NP_  = 576;
constexpr int D_   = 768;
constexpr int DH_  = 64;
constexpr int NRELC = 2209;
constexpr int BPAD = 640;
constexpr int MR   = B_ * N_;             // 18464

#define CDIV(a,b) (((a)+(b)-1)/(b))

__device__ float g_q[(size_t)B_*H_*N_*DH_];
__device__ float g_k[(size_t)B_*H_*N_*DH_];
__device__ float g_v[(size_t)B_*H_*N_*DH_];
__device__ float g_bias[(size_t)H_*BPAD*BPAD];
__device__ float g_ao[(size_t)MR*D_];

// packed f32x2 helpers --------------------------------------------------------
__device__ __forceinline__ u64 pk2(float a, float b) {
    u64 r; asm("mov.b64 %0,{%1,%2};" : "=l"(r) : "f"(a), "f"(b)); return r;
}
__device__ __forceinline__ float2 unpk(u64 v) {
    float2 r; asm("mov.b64 {%0,%1},%2;" : "=f"(r.x), "=f"(r.y) : "l"(v)); return r;
}
__device__ __forceinline__ void fma2(u64& d, u64 a, u64 b) {
    asm("fma.rn.f32x2 %0,%1,%2,%0;" : "+l"(d) : "l"(a), "l"(b));
}
__device__ __forceinline__ void mul2(u64& d, u64 a) {
    asm("mul.rn.f32x2 %0,%0,%1;" : "+l"(d) : "l"(a));
}

// ---------------------------------------------------------------------------
// K0: bias table (12 x 640 x 640, zero padded)
// ---------------------------------------------------------------------------
__global__ void bias_build(const float* __restrict__ b1, const float* __restrict__ b2,
                           const float* __restrict__ b3, const int* __restrict__ map) {
    int idx = blockIdx.x * blockDim.x + threadIdx.x;
    constexpr int TOT = H_ * BPAD * BPAD;
    if (idx >= TOT) return;
    int h = idx / (BPAD * BPAD);
    int r = idx - h * (BPAD * BPAD);
    int i = r / BPAD;
    int j = r - i * BPAD;
    float v = 0.f;
    if (i < N_ && j < N_) {
        if (i == NP_)      v = b1[h * N_ + j];
        else if (j == 0)   v = b2[h * NP_ + i];
        else               v = b3[h * NRELC + map[i * NP_ + (j - 1)]];
    }
    g_bias[idx] = v;
}

// ---------------------------------------------------------------------------
// GEMM 128x128 tile, BK=16, 256 threads, 8x8 microtile via fma.rn.f32x2.
// C[m][c] = dot(Arow[m,:], W[c,:]).
// WHICH==0: A = x (kernel arg), epilogue scatters to g_q/g_k/g_v (Q x0.125)
// WHICH==1: A = g_ao (device global, read in device code), epilogue adds bias
// ---------------------------------------------------------------------------
template<int WHICH>
__global__ void __launch_bounds__(256, 2) gemm128(const float* __restrict__ A,
                                                  const float* __restrict__ W,
                                                  const float* __restrict__ pbias,
                                                  float* __restrict__ out) {
    __shared__ float As[16][128];
    __shared__ float Bs[16][128];
    const float* __restrict__ Abase = (WHICH == 0) ? A : (const float*)g_ao;
    const int m0 = blockIdx.y * 128;
    const int c0 = blockIdx.x * 128;
    const int t  = threadIdx.x;
    const int lr = t >> 1;            // 0..127
    const int lk = (t & 1) * 8;       // 0 or 8
    const int tx = t & 15;
    const int ty = t >> 4;
    const bool aval = (m0 + lr) < MR;
    const float* Ap = Abase + (size_t)(m0 + lr) * D_ + lk;
    const float* Wp = W + (size_t)(c0 + lr) * D_ + lk;
    const float4 z4 = make_float4(0.f, 0.f, 0.f, 0.f);

    float4 pa0 = aval ? *(const float4*)(Ap)     : z4;
    float4 pa1 = aval ? *(const float4*)(Ap + 4) : z4;
    float4 pb0 = *(const float4*)(Wp);
    float4 pb1 = *(const float4*)(Wp + 4);

    u64 acc[8][4];
    #pragma unroll
    for (int i = 0; i < 8; i++)
        #pragma unroll
        for (int j = 0; j < 4; j++) acc[i][j] = 0ull;

    for (int kt = 0; kt < 48; kt++) {
        __syncthreads();
        As[lk+0][lr] = pa0.x; As[lk+1][lr] = pa0.y; As[lk+2][lr] = pa0.z; As[lk+3][lr] = pa0.w;
        As[lk+4][lr] = pa1.x; As[lk+5][lr] = pa1.y; As[lk+6][lr] = pa1.z; As[lk+7][lr] = pa1.w;
        Bs[lk+0][lr] = pb0.x; Bs[lk+1][lr] = pb0.y; Bs[lk+2][lr] = pb0.z; Bs[lk+3][lr] = pb0.w;
        Bs[lk+4][lr] = pb1.x; Bs[lk+5][lr] = pb1.y; Bs[lk+6][lr] = pb1.z; Bs[lk+7][lr] = pb1.w;
        __syncthreads();
        if (kt < 47) {
            const float* Ak = Ap + (kt + 1) * 16;
            const float* Wk = Wp + (kt + 1) * 16;
            pa0 = aval ? *(const float4*)(Ak)     : z4;
            pa1 = aval ? *(const float4*)(Ak + 4) : z4;
            pb0 = *(const float4*)(Wk);
            pb1 = *(const float4*)(Wk + 4);
        }
        #pragma unroll
        for (int kk = 0; kk < 16; kk++) {
            float4 a0 = *(const float4*)&As[kk][ty * 4];
            float4 a1 = *(const float4*)&As[kk][64 + ty * 4];
            u64 b0 = *(const u64*)&Bs[kk][tx * 4];
            u64 b1 = *(const u64*)&Bs[kk][tx * 4 + 2];
            u64 b2 = *(const u64*)&Bs[kk][64 + tx * 4];
            u64 b3 = *(const u64*)&Bs[kk][64 + tx * 4 + 2];
            u64 ad;
            ad = pk2(a0.x, a0.x); fma2(acc[0][0],ad,b0); fma2(acc[0][1],ad,b1); fma2(acc[0][2],ad,b2); fma2(acc[0][3],ad,b3);
            ad = pk2(a0.y, a0.y); fma2(acc[1][0],ad,b0); fma2(acc[1][1],ad,b1); fma2(acc[1][2],ad,b2); fma2(acc[1][3],ad,b3);
            ad = pk2(a0.z, a0.z); fma2(acc[2][0],ad,b0); fma2(acc[2][1],ad,b1); fma2(acc[2][2],ad,b2); fma2(acc[2][3],ad,b3);
            ad = pk2(a0.w, a0.w); fma2(acc[3][0],ad,b0); fma2(acc[3][1],ad,b1); fma2(acc[3][2],ad,b2); fma2(acc[3][3],ad,b3);
            ad = pk2(a1.x, a1.x); fma2(acc[4][0],ad,b0); fma2(acc[4][1],ad,b1); fma2(acc[4][2],ad,b2); fma2(acc[4][3],ad,b3);
            ad = pk2(a1.y, a1.y); fma2(acc[5][0],ad,b0); fma2(acc[5][1],ad,b1); fma2(acc[5][2],ad,b2); fma2(acc[5][3],ad,b3);
            ad = pk2(a1.z, a1.z); fma2(acc[6][0],ad,b0); fma2(acc[6][1],ad,b1); fma2(acc[6][2],ad,b2); fma2(acc[6][3],ad,b3);
            ad = pk2(a1.w, a1.w); fma2(acc[7][0],ad,b0); fma2(acc[7][1],ad,b1); fma2(acc[7][2],ad,b2); fma2(acc[7][3],ad,b3);
        }
    }

    if (WHICH == 0) {
        const int s  = c0 / D_;
        const int h0 = (c0 - s * D_) / DH_;       // tile covers heads h0, h0+1
        const float scl = (s == 0) ? 0.125f : 1.0f;
        float* dst = (s == 0) ? g_q : (s == 1) ? g_k : g_v;
        #pragma unroll
        for (int r = 0; r < 8; r++) {
            int m = m0 + ((r < 4) ? (ty * 4 + r) : (64 + ty * 4 + r - 4));
            if (m >= MR) continue;
            int bb = m / N_, n = m - bb * N_;
            float2 v0 = unpk(acc[r][0]), v1 = unpk(acc[r][1]);
            float2 v2 = unpk(acc[r][2]), v3 = unpk(acc[r][3]);
            size_t off0 = (((size_t)(bb * H_ + h0)) * N_ + n) * DH_ + tx * 4;
            *(float4*)(dst + off0) = make_float4(v0.x*scl, v0.y*scl, v1.x*scl, v1.y*scl);
            size_t off1 = (((size_t)(bb * H_ + h0 + 1)) * N_ + n) * DH_ + tx * 4;
            *(float4*)(dst + off1) = make_float4(v2.x*scl, v2.y*scl, v3.x*scl, v3.y*scl);
        }
    } else {
        float4 bva = *(const float4*)(pbias + c0 + tx * 4);
        float4 bvb = *(const float4*)(pbias + c0 + 64 + tx * 4);
        #pragma unroll
        for (int r = 0; r < 8; r++) {
            int m = m0 + ((r < 4) ? (ty * 4 + r) : (64 + ty * 4 + r - 4));
            if (m >= MR) continue;
            float2 v0 = unpk(acc[r][0]), v1 = unpk(acc[r][1]);
            float2 v2 = unpk(acc[r][2]), v3 = unpk(acc[r][3]);
            *(float4*)(out + (size_t)m * D_ + c0 + tx * 4) =
                make_float4(v0.x+bva.x, v0.y+bva.y, v1.x+bva.z, v1.y+bva.w);
            *(float4*)(out + (size_t)m * D_ + c0 + 64 + tx * 4) =
                make_float4(v2.x+bvb.x, v2.y+bvb.y, v3.x+bvb.z, v3.y+bvb.w);
        }
    }
}

// ---------------------------------------------------------------------------
// K2: fused attention, 64x64 tiles, 4x4 microtile, fma.rn.f32x2 inner loops.
// Shared row stride 68 (16B-aligned rows for float4/u64 loads).
// ---------------------------------------------------------------------------
constexpr int SST = 68;

__global__ void __launch_bounds__(256) attn_kernel() {
    extern __shared__ float sh[];
    float* Qs = sh;
    float* Ks = sh + 64 * SST;
    float* Vs = sh + 2 * 64 * SST;
    float* Ps = sh + 3 * 64 * SST;

    const int bh = blockIdx.y;
    const int h  = bh % H_;
    const int i0 = blockIdx.x * 64;
    const int t  = threadIdx.x;
    const int ty4 = (t >> 4) * 4;
    const int tx4 = (t & 15) * 4;

    const size_t base = (size_t)bh * N_ * DH_;
    const float* qb = g_q + base;
    const float* kb = g_k + base;
    const float* vb = g_v + base;

    // load Q tile transposed -> Qs[d][i]
    {
        const int rbase = (t >> 4);
        const int c4 = (t & 15) * 4;
        #pragma unroll
        for (int rr = 0; rr < 4; rr++) {
            int r = rr * 16 + rbase;
            int gi = i0 + r;
            float4 v = (gi < N_) ? *(const float4*)(qb + (size_t)gi * DH_ + c4)
                                 : make_float4(0.f,0.f,0.f,0.f);
            Qs[(c4+0)*SST + r] = v.x;
            Qs[(c4+1)*SST + r] = v.y;
            Qs[(c4+2)*SST + r] = v.z;
            Qs[(c4+3)*SST + r] = v.w;
        }
    }

    float m_[4], l_[4];
    u64 o2[4][2];
    #pragma unroll
    for (int a = 0; a < 4; a++) {
        m_[a] = -1e30f; l_[a] = 0.f;
        o2[a][0] = 0ull; o2[a][1] = 0ull;
    }

    const float* brow = g_bias + ((size_t)h * BPAD + i0 + ty4) * BPAD + tx4;

    for (int kt = 0; kt < 10; kt++) {
        const int j0 = kt * 64;
        __syncthreads();
        {
            const int rbase = (t >> 4);
            const int c4 = (t & 15) * 4;
            #pragma unroll
            for (int rr = 0; rr < 4; rr++) {
                int r = rr * 16 + rbase;
                int gj = j0 + r;
                float4 kv = (gj < N_) ? *(const float4*)(kb + (size_t)gj * DH_ + c4)
                                      : make_float4(0.f,0.f,0.f,0.f);
                Ks[(c4+0)*SST + r] = kv.x;
                Ks[(c4+1)*SST + r] = kv.y;
                Ks[(c4+2)*SST + r] = kv.z;
                Ks[(c4+3)*SST + r] = kv.w;
                float4 vv = (gj < N_) ? *(const float4*)(vb + (size_t)gj * DH_ + c4)
                                      : make_float4(0.f,0.f,0.f,0.f);
                Vs[r*SST + c4+0] = vv.x;
                Vs[r*SST + c4+1] = vv.y;
                Vs[r*SST + c4+2] = vv.z;
                Vs[r*SST + c4+3] = vv.w;
            }
        }
        __syncthreads();

        // S = Q K^T via f32x2
        u64 s2[4][2];
        #pragma unroll
        for (int a = 0; a < 4; a++) { s2[a][0] = 0ull; s2[a][1] = 0ull; }

        #pragma unroll 8
        for (int d = 0; d < 64; d++) {
            float4 q = *(const float4*)&Qs[d*SST + ty4];
            u64 k0 = *(const u64*)&Ks[d*SST + tx4];
            u64 k1 = *(const u64*)&Ks[d*SST + tx4 + 2];
            u64 qd;
            qd = pk2(q.x, q.x); fma2(s2[0][0], qd, k0); fma2(s2[0][1], qd, k1);
            qd = pk2(q.y, q.y); fma2(s2[1][0], qd, k0); fma2(s2[1][1], qd, k1);
            qd = pk2(q.z, q.z); fma2(s2[2][0], qd, k0); fma2(s2[2][1], qd, k1);
            qd = pk2(q.w, q.w); fma2(s2[3][0], qd, k0); fma2(s2[3][1], qd, k1);
        }

        // unpack + bias + mask
        float s[4][4];
        #pragma unroll
        for (int a = 0; a < 4; a++) {
            float2 lo = unpk(s2[a][0]), hi = unpk(s2[a][1]);
            float4 bv = *(const float4*)(brow + (size_t)a * BPAD + j0);
            s[a][0] = lo.x + bv.x; s[a][1] = lo.y + bv.y;
            s[a][2] = hi.x + bv.z; s[a][3] = hi.y + bv.w;
        }
        #pragma unroll
        for (int b = 0; b < 4; b++) {
            if (j0 + tx4 + b >= N_) {
                s[0][b] = -1e30f; s[1][b] = -1e30f; s[2][b] = -1e30f; s[3][b] = -1e30f;
            }
        }

        // online softmax
        #pragma unroll
        for (int a = 0; a < 4; a++) {
            float mx = fmaxf(fmaxf(s[a][0], s[a][1]), fmaxf(s[a][2], s[a][3]));
            #pragma unroll
            for (int off = 8; off; off >>= 1)
                mx = fmaxf(mx, __shfl_xor_sync(0xffffffffu, mx, off));
            float mn = fmaxf(m_[a], mx);
            float corr = __expf(m_[a] - mn);
            float rs = 0.f;
            #pragma unroll
            for (int b = 0; b < 4; b++) {
                float p = __expf(s[a][b] - mn);
                s[a][b] = p;
                rs += p;
            }
            #pragma unroll
            for (int off = 8; off; off >>= 1)
                rs += __shfl_xor_sync(0xffffffffu, rs, off);
            l_[a] = l_[a] * corr + rs;
            m_[a] = mn;
            u64 c2 = pk2(corr, corr);
            mul2(o2[a][0], c2);
            mul2(o2[a][1], c2);
        }

        // stage P transposed -> Ps[j][i]
        #pragma unroll
        for (int b = 0; b < 4; b++)
            #pragma unroll
            for (int a = 0; a < 4; a++)
                Ps[(tx4+b)*SST + ty4 + a] = s[a][b];
        __syncthreads();

        // O += P V via f32x2
        #pragma unroll 8
        for (int j = 0; j < 64; j++) {
            float4 p = *(const float4*)&Ps[j*SST + ty4];
            u64 v0 = *(const u64*)&Vs[j*SST + tx4];
            u64 v1 = *(const u64*)&Vs[j*SST + tx4 + 2];
            u64 pd;
            pd = pk2(p.x, p.x); fma2(o2[0][0], pd, v0); fma2(o2[0][1], pd, v1);
            pd = pk2(p.y, p.y); fma2(o2[1][0], pd, v0); fma2(o2[1][1], pd, v1);
            pd = pk2(p.z, p.z); fma2(o2[2][0], pd, v0); fma2(o2[2][1], pd, v1);
            pd = pk2(p.w, p.w); fma2(o2[3][0], pd, v0); fma2(o2[3][1], pd, v1);
        }
    }

    // epilogue
    const int b = bh / H_;
    #pragma unroll
    for (int a = 0; a < 4; a++) {
        int gi = i0 + ty4 + a;
        if (gi >= N_) continue;
        float inv = 1.f / l_[a];
        float2 lo = unpk(o2[a][0]), hi = unpk(o2[a][1]);
        size_t off = ((size_t)b * N_ + gi) * D_ + h * DH_ + tx4;
        *(float4*)(g_ao + off) = make_float4(lo.x*inv, lo.y*inv, hi.x*inv, hi.y*inv);
    }
}

// ---------------------------------------------------------------------------
extern "C" void kernel_launch(void* const* d_in, const int* in_sizes, int n_in,
                              void* d_out, int out_size) {
    (void)in_sizes; (void)n_in; (void)out_size;
    const float* x    = (const float*)d_in[0];
    const float* qkvw = (const float*)d_in[1];
    const float* pw   = (const float*)d_in[2];
    const float* pb   = (const float*)d_in[3];
    const float* b1   = (const float*)d_in[4];
    const float* b2   = (const float*)d_in[5];
    const float* b3   = (const float*)d_in[6];
    const int*   map  = (const int*)d_in[7];
    float* out = (float*)d_out;

    const int attn_smem = 4 * 64 * SST * (int)sizeof(float);   // 69,632 B
    cudaFuncSetAttribute(attn_kernel, cudaFuncAttributeMaxDynamicSharedMemorySize, attn_smem);

    bias_build<<<CDIV(H_ * BPAD * BPAD, 256), 256>>>(b1, b2, b3, map);
    gemm128<0><<<dim3(2304 / 128, CDIV(MR, 128)), 256>>>(x, qkvw, nullptr, nullptr);
    attn_kernel<<<dim3(CDIV(N_, 64), B_ * H_), 256, attn_smem>>>();
    gemm128<1><<<dim3(D_ / 128, CDIV(MR, 128)), 256>>>(nullptr, pw, pb, out);
}

// round 5
// speedup vs baseline: 2.1167x; 1.3815x over previous
#include <cuda_runtime.h>
#include <cuda_bf16.h>
#include <cstdint>

// ---------------------------------------------------------------------------
// T5RelativeAttention  (B=32, N=577, DIM=768, H=12, Dh=64)
// Round 5: warp-level mma.sync bf16x3 emulated-fp32 GEMMs (tcgen05 is not
// available: harness compiles PTX at compute_103, no 'a' features).
// Attention stays SIMT f32x2.
// ---------------------------------------------------------------------------

using u64 = unsigned long long;

constexpr int B_   = 32;
constexpr int H_   = 12;
constexpr int N_   = 577;
constexpr int NP_  = 576;
constexpr int D_   = 768;
constexpr int DH_  = 64;
constexpr int NRELC = 2209;
constexpr int BPAD = 640;
constexpr int MR   = B_ * N_;             // 18464

#define CDIV(a,b) (((a)+(b)-1)/(b))

__device__ float g_q[(size_t)B_*H_*N_*DH_];
__device__ float g_k[(size_t)B_*H_*N_*DH_];
__device__ float g_v[(size_t)B_*H_*N_*DH_];
__device__ float g_bias[(size_t)H_*BPAD*BPAD];
// bf16 hi/lo splits
__device__ __nv_bfloat16 g_x0[(size_t)MR*D_],   g_x1[(size_t)MR*D_];
__device__ __nv_bfloat16 g_w0[(size_t)3*D_*D_], g_w1[(size_t)3*D_*D_];
__device__ __nv_bfloat16 g_p0[(size_t)D_*D_],   g_p1[(size_t)D_*D_];
__device__ __nv_bfloat16 g_ao0[(size_t)MR*D_],  g_ao1[(size_t)MR*D_];

// ---------------- f32x2 helpers (attention) --------------------------------
__device__ __forceinline__ u64 pk2(float a, float b) {
    u64 r; asm("mov.b64 %0,{%1,%2};" : "=l"(r) : "f"(a), "f"(b)); return r;
}
__device__ __forceinline__ float2 unpk(u64 v) {
    float2 r; asm("mov.b64 {%0,%1},%2;" : "=f"(r.x), "=f"(r.y) : "l"(v)); return r;
}
__device__ __forceinline__ void fma2(u64& d, u64 a, u64 b) {
    asm("fma.rn.f32x2 %0,%1,%2,%0;" : "+l"(d) : "l"(a), "l"(b));
}
__device__ __forceinline__ void mul2(u64& d, u64 a) {
    asm("mul.rn.f32x2 %0,%0,%1;" : "+l"(d) : "l"(a));
}

// ---------------- mma.sync / cp.async helpers -------------------------------
__device__ __forceinline__ void mma16816(float* d, const uint32_t* a, const uint32_t* b) {
    asm volatile(
        "mma.sync.aligned.m16n8k16.row.col.f32.bf16.bf16.f32 "
        "{%0,%1,%2,%3},{%4,%5,%6,%7},{%8,%9},{%0,%1,%2,%3};"
        : "+f"(d[0]), "+f"(d[1]), "+f"(d[2]), "+f"(d[3])
        : "r"(a[0]), "r"(a[1]), "r"(a[2]), "r"(a[3]), "r"(b[0]), "r"(b[1]));
}
__device__ __forceinline__ uint32_t s2u(const void* p) {
    uint32_t a;
    asm("{ .reg .u64 t; cvta.to.shared.u64 t, %1; cvt.u32.u64 %0, t; }" : "=r"(a) : "l"(p));
    return a;
}
__device__ __forceinline__ void cpa16(uint32_t dst, const void* src, int srcbytes) {
    asm volatile("cp.async.cg.shared.global [%0], [%1], 16, %2;"
                 :: "r"(dst), "l"(src), "r"(srcbytes));
}
__device__ __forceinline__ void cpa_commit() {
    asm volatile("cp.async.commit_group;" ::: "memory");
}
template<int N>
__device__ __forceinline__ void cpa_wait() {
    asm volatile("cp.async.wait_group %0;" :: "n"(N) : "memory");
}

// ---------------------------------------------------------------------------
// K0: bias table (12 x 640 x 640, zero padded)
// ---------------------------------------------------------------------------
__global__ void bias_build(const float* __restrict__ b1, const float* __restrict__ b2,
                           const float* __restrict__ b3, const int* __restrict__ map) {
    int idx = blockIdx.x * blockDim.x + threadIdx.x;
    constexpr int TOT = H_ * BPAD * BPAD;
    if (idx >= TOT) return;
    int h = idx / (BPAD * BPAD);
    int r = idx - h * (BPAD * BPAD);
    int i = r / BPAD;
    int j = r - i * BPAD;
    float v = 0.f;
    if (i < N_ && j < N_) {
        if (i == NP_)      v = b1[h * N_ + j];
        else if (j == 0)   v = b2[h * NP_ + i];
        else               v = b3[h * NRELC + map[i * NP_ + (j - 1)]];
    }
    g_bias[idx] = v;
}

// ---------------------------------------------------------------------------
// K_split: fp32 -> (hi, lo) bf16.
// ---------------------------------------------------------------------------
template<int SRC>
__global__ void split_k(const float* __restrict__ src) {
    __nv_bfloat16 *hi, *lo; size_t n;
    if (SRC == 0)      { hi = g_x0; lo = g_x1; n = (size_t)MR * D_; }
    else if (SRC == 1) { hi = g_w0; lo = g_w1; n = (size_t)3 * D_ * D_; }
    else               { hi = g_p0; lo = g_p1; n = (size_t)D_ * D_; }
    size_t i = (size_t)blockIdx.x * blockDim.x + threadIdx.x;
    if (i * 4 >= n) return;
    float4 v = *(const float4*)(src + i * 4);
    float vv[4] = {v.x, v.y, v.z, v.w};
    __nv_bfloat16 hb[4], lb[4];
    #pragma unroll
    for (int j = 0; j < 4; j++) {
        hb[j] = __float2bfloat16(vv[j]);
        lb[j] = __float2bfloat16(vv[j] - __bfloat162float(hb[j]));
    }
    *(uint2*)(hi + i * 4) = *(uint2*)hb;
    *(uint2*)(lo + i * 4) = *(uint2*)lb;
}

// ---------------------------------------------------------------------------
// mma.sync GEMM: 128x128 CTA tile, BK=32, 8 warps (2x4), warp tile 64x32.
// bf16x3 emulation: D += Ahi*Bhi + Ahi*Blo + Alo*Bhi.
// SMEM per buffer: A0,A1,B0,B1 each 128 rows x 40 bf16 (80B stride) = 10240B.
// Double buffered via cp.async (2 x 40960B).
// WHICH==0: A=(g_x0,g_x1), B=(g_w0,g_w1), scatter q/k/v (Q x0.125).
// WHICH==1: A=(g_ao0,g_ao1), B=(g_p0,g_p1), +bias -> out.
// ---------------------------------------------------------------------------
constexpr int APAD = 40;                       // bf16 row stride (80B)
constexpr int MATB = 128 * APAD * 2;           // 10240 bytes per matrix
constexpr int BUFB = 4 * MATB;                 // 40960 bytes per buffer
constexpr int GEMM_SMEM = 2 * BUFB;            // 81920

template<int WHICH>
__global__ void __launch_bounds__(256, 1)
gemm_mma(const float* __restrict__ pbias, float* __restrict__ out) {
    extern __shared__ char sm[];
    const uint32_t sb = s2u(sm);
    const int t = threadIdx.x;
    const int lane = t & 31, wid = t >> 5;
    const int wm = wid >> 2, wn = wid & 3;      // 2 x 4 warp grid
    const int m0 = blockIdx.y * 128;
    const int c0 = blockIdx.x * 128;

    const __nv_bfloat16 *A0g, *A1g, *B0g, *B1g;
    if (WHICH == 0) { A0g = g_x0;  A1g = g_x1;  B0g = g_w0; B1g = g_w1; }
    else            { A0g = g_ao0; A1g = g_ao1; B0g = g_p0; B1g = g_p1; }

    // loader mapping: thread covers rows (t>>2) and (t>>2)+64, 8 bf16 at kc
    const int mrow = t >> 2;
    const int kc   = (t & 3) * 8;
    const bool av0 = (m0 + mrow) < MR;
    const bool av1 = (m0 + mrow + 64) < MR;
    const uint32_t soff0 = (uint32_t)(mrow * 80 + kc * 2);
    const uint32_t soff1 = (uint32_t)((mrow + 64) * 80 + kc * 2);

    float acc[4][4][4];
    #pragma unroll
    for (int i = 0; i < 4; i++)
        #pragma unroll
        for (int j = 0; j < 4; j++)
            #pragma unroll
            for (int q = 0; q < 4; q++) acc[i][j][q] = 0.f;

    auto issue = [&](int buf, int kt) {
        const int ko = kt * 32 + kc;
        const uint32_t bs = sb + buf * BUFB;
        size_t a0 = (size_t)(m0 + mrow) * D_ + ko;
        size_t a1 = (size_t)(m0 + mrow + 64) * D_ + ko;
        size_t b0 = (size_t)(c0 + mrow) * D_ + ko;
        size_t b1 = (size_t)(c0 + mrow + 64) * D_ + ko;
        cpa16(bs + soff0,            A0g + a0, av0 ? 16 : 0);
        cpa16(bs + soff1,            A0g + a1, av1 ? 16 : 0);
        cpa16(bs + MATB + soff0,     A1g + a0, av0 ? 16 : 0);
        cpa16(bs + MATB + soff1,     A1g + a1, av1 ? 16 : 0);
        cpa16(bs + 2*MATB + soff0,   B0g + b0, 16);
        cpa16(bs + 2*MATB + soff1,   B0g + b1, 16);
        cpa16(bs + 3*MATB + soff0,   B1g + b0, 16);
        cpa16(bs + 3*MATB + soff1,   B1g + b1, 16);
    };

    issue(0, 0);
    cpa_commit();

    const int ar = wm * 64 + (lane >> 2);       // A fragment base row
    const int br = wn * 32 + (lane >> 2);       // B fragment base row
    const int fc = (lane & 3) * 2;              // fragment k column

    constexpr int NK = 24;                      // 768 / 32
    for (int kt = 0; kt < NK; kt++) {
        const int buf = kt & 1;
        if (kt + 1 < NK) {
            issue(buf ^ 1, kt + 1);
            cpa_commit();
            cpa_wait<1>();
        } else {
            cpa_wait<0>();
        }
        __syncthreads();

        const __nv_bfloat16* sA0 = (const __nv_bfloat16*)(sm + buf * BUFB);
        const __nv_bfloat16* sA1 = (const __nv_bfloat16*)(sm + buf * BUFB + MATB);
        const __nv_bfloat16* sB0 = (const __nv_bfloat16*)(sm + buf * BUFB + 2*MATB);
        const __nv_bfloat16* sB1 = (const __nv_bfloat16*)(sm + buf * BUFB + 3*MATB);

        #pragma unroll
        for (int ks = 0; ks < 2; ks++) {
            const int kb = ks * 16 + fc;
            uint32_t ah[4][4], al[4][4], bh[4][2], bl[4][2];
            #pragma unroll
            for (int am = 0; am < 4; am++) {
                int base = (ar + am * 16) * APAD + kb;
                ah[am][0] = *(const uint32_t*)&sA0[base];
                ah[am][1] = *(const uint32_t*)&sA0[base + 8 * APAD];
                ah[am][2] = *(const uint32_t*)&sA0[base + 8];
                ah[am][3] = *(const uint32_t*)&sA0[base + 8 * APAD + 8];
                al[am][0] = *(const uint32_t*)&sA1[base];
                al[am][1] = *(const uint32_t*)&sA1[base + 8 * APAD];
                al[am][2] = *(const uint32_t*)&sA1[base + 8];
                al[am][3] = *(const uint32_t*)&sA1[base + 8 * APAD + 8];
            }
            #pragma unroll
            for (int an = 0; an < 4; an++) {
                int base = (br + an * 8) * APAD + kb;
                bh[an][0] = *(const uint32_t*)&sB0[base];
                bh[an][1] = *(const uint32_t*)&sB0[base + 8];
                bl[an][0] = *(const uint32_t*)&sB1[base];
                bl[an][1] = *(const uint32_t*)&sB1[base + 8];
            }
            #pragma unroll
            for (int am = 0; am < 4; am++)
                #pragma unroll
                for (int an = 0; an < 4; an++) {
                    mma16816(acc[am][an], ah[am], bh[an]);
                    mma16816(acc[am][an], ah[am], bl[an]);
                    mma16816(acc[am][an], al[am], bh[an]);
                }
        }
        __syncthreads();
    }

    // ---------------- epilogue: direct register stores ----------------------
    #pragma unroll
    for (int am = 0; am < 4; am++) {
        #pragma unroll
        for (int an = 0; an < 4; an++) {
            int r0 = m0 + wm * 64 + am * 16 + (lane >> 2);
            int cc = wn * 32 + an * 8 + (lane & 3) * 2;   // col within tile
            if (WHICH == 0) {
                const int s  = c0 / D_;
                const int w  = (c0 - s * D_) + cc;
                const int hh = w >> 6, d = w & 63;
                float* dst = (s == 0) ? g_q : (s == 1) ? g_k : g_v;
                const float scl = (s == 0) ? 0.125f : 1.0f;
                #pragma unroll
                for (int rr = 0; rr < 2; rr++) {
                    int r = r0 + rr * 8;
                    if (r < MR) {
                        int bb = r / N_, n = r - bb * N_;
                        size_t off = (((size_t)(bb * H_ + hh)) * N_ + n) * DH_ + d;
                        float2 v = make_float2(acc[am][an][rr*2] * scl,
                                               acc[am][an][rr*2+1] * scl);
                        *(float2*)(dst + off) = v;
                    }
                }
            } else {
                float2 bv = *(const float2*)(pbias + c0 + cc);
                #pragma unroll
                for (int rr = 0; rr < 2; rr++) {
                    int r = r0 + rr * 8;
                    if (r < MR) {
                        float2 v = make_float2(acc[am][an][rr*2]   + bv.x,
                                               acc[am][an][rr*2+1] + bv.y);
                        *(float2*)(out + (size_t)r * D_ + c0 + cc) = v;
                    }
                }
            }
        }
    }
}

// ---------------------------------------------------------------------------
// K2: fused attention (SIMT f32x2), epilogue writes bf16 splits g_ao0/1.
// ---------------------------------------------------------------------------
constexpr int SST = 68;

__global__ void __launch_bounds__(256) attn_kernel() {
    extern __shared__ float sh[];
    float* Qs = sh;
    float* Ks = sh + 64 * SST;
    float* Vs = sh + 2 * 64 * SST;
    float* Ps = sh + 3 * 64 * SST;

    const int bh = blockIdx.y;
    const int h  = bh % H_;
    const int i0 = blockIdx.x * 64;
    const int t  = threadIdx.x;
    const int ty4 = (t >> 4) * 4;
    const int tx4 = (t & 15) * 4;

    const size_t base = (size_t)bh * N_ * DH_;
    const float* qb = g_q + base;
    const float* kb = g_k + base;
    const float* vb = g_v + base;

    {
        const int rbase = (t >> 4);
        const int c4 = (t & 15) * 4;
        #pragma unroll
        for (int rr = 0; rr < 4; rr++) {
            int r = rr * 16 + rbase;
            int gi = i0 + r;
            float4 v = (gi < N_) ? *(const float4*)(qb + (size_t)gi * DH_ + c4)
                                 : make_float4(0.f,0.f,0.f,0.f);
            Qs[(c4+0)*SST + r] = v.x;
            Qs[(c4+1)*SST + r] = v.y;
            Qs[(c4+2)*SST + r] = v.z;
            Qs[(c4+3)*SST + r] = v.w;
        }
    }

    float m_[4], l_[4];
    u64 o2[4][2];
    #pragma unroll
    for (int a = 0; a < 4; a++) {
        m_[a] = -1e30f; l_[a] = 0.f;
        o2[a][0] = 0ull; o2[a][1] = 0ull;
    }

    const float* brow = g_bias + ((size_t)h * BPAD + i0 + ty4) * BPAD + tx4;

    for (int kt = 0; kt < 10; kt++) {
        const int j0 = kt * 64;
        __syncthreads();
        {
            const int rbase = (t >> 4);
            const int c4 = (t & 15) * 4;
            #pragma unroll
            for (int rr = 0; rr < 4; rr++) {
                int r = rr * 16 + rbase;
                int gj = j0 + r;
                float4 kv = (gj < N_) ? *(const float4*)(kb + (size_t)gj * DH_ + c4)
                                      : make_float4(0.f,0.f,0.f,0.f);
                Ks[(c4+0)*SST + r] = kv.x;
                Ks[(c4+1)*SST + r] = kv.y;
                Ks[(c4+2)*SST + r] = kv.z;
                Ks[(c4+3)*SST + r] = kv.w;
                float4 vv = (gj < N_) ? *(const float4*)(vb + (size_t)gj * DH_ + c4)
                                      : make_float4(0.f,0.f,0.f,0.f);
                Vs[r*SST + c4+0] = vv.x;
                Vs[r*SST + c4+1] = vv.y;
                Vs[r*SST + c4+2] = vv.z;
                Vs[r*SST + c4+3] = vv.w;
            }
        }
        __syncthreads();

        u64 s2[4][2];
        #pragma unroll
        for (int a = 0; a < 4; a++) { s2[a][0] = 0ull; s2[a][1] = 0ull; }

        #pragma unroll 8
        for (int d = 0; d < 64; d++) {
            float4 q = *(const float4*)&Qs[d*SST + ty4];
            u64 k0 = *(const u64*)&Ks[d*SST + tx4];
            u64 k1 = *(const u64*)&Ks[d*SST + tx4 + 2];
            u64 qd;
            qd = pk2(q.x, q.x); fma2(s2[0][0], qd, k0); fma2(s2[0][1], qd, k1);
            qd = pk2(q.y, q.y); fma2(s2[1][0], qd, k0); fma2(s2[1][1], qd, k1);
            qd = pk2(q.z, q.z); fma2(s2[2][0], qd, k0); fma2(s2[2][1], qd, k1);
            qd = pk2(q.w, q.w); fma2(s2[3][0], qd, k0); fma2(s2[3][1], qd, k1);
        }

        float s[4][4];
        #pragma unroll
        for (int a = 0; a < 4; a++) {
            float2 lo = unpk(s2[a][0]), hi = unpk(s2[a][1]);
            float4 bv = *(const float4*)(brow + (size_t)a * BPAD + j0);
            s[a][0] = lo.x + bv.x; s[a][1] = lo.y + bv.y;
            s[a][2] = hi.x + bv.z; s[a][3] = hi.y + bv.w;
        }
        #pragma unroll
        for (int b = 0; b < 4; b++) {
            if (j0 + tx4 + b >= N_) {
                s[0][b] = -1e30f; s[1][b] = -1e30f; s[2][b] = -1e30f; s[3][b] = -1e30f;
            }
        }

        #pragma unroll
        for (int a = 0; a < 4; a++) {
            float mx = fmaxf(fmaxf(s[a][0], s[a][1]), fmaxf(s[a][2], s[a][3]));
            #pragma unroll
            for (int off = 8; off; off >>= 1)
                mx = fmaxf(mx, __shfl_xor_sync(0xffffffffu, mx, off));
            float mn = fmaxf(m_[a], mx);
            float corr = __expf(m_[a] - mn);
            float rs = 0.f;
            #pragma unroll
            for (int b = 0; b < 4; b++) {
                float p = __expf(s[a][b] - mn);
                s[a][b] = p;
                rs += p;
            }
            #pragma unroll
            for (int off = 8; off; off >>= 1)
                rs += __shfl_xor_sync(0xffffffffu, rs, off);
            l_[a] = l_[a] * corr + rs;
            m_[a] = mn;
            u64 c2 = pk2(corr, corr);
            mul2(o2[a][0], c2);
            mul2(o2[a][1], c2);
        }

        #pragma unroll
        for (int b = 0; b < 4; b++)
            #pragma unroll
            for (int a = 0; a < 4; a++)
                Ps[(tx4+b)*SST + ty4 + a] = s[a][b];
        __syncthreads();

        #pragma unroll 8
        for (int j = 0; j < 64; j++) {
            float4 p = *(const float4*)&Ps[j*SST + ty4];
            u64 v0 = *(const u64*)&Vs[j*SST + tx4];
            u64 v1 = *(const u64*)&Vs[j*SST + tx4 + 2];
            u64 pd;
            pd = pk2(p.x, p.x); fma2(o2[0][0], pd, v0); fma2(o2[0][1], pd, v1);
            pd = pk2(p.y, p.y); fma2(o2[1][0], pd, v0); fma2(o2[1][1], pd, v1);
            pd = pk2(p.z, p.z); fma2(o2[2][0], pd, v0); fma2(o2[2][1], pd, v1);
            pd = pk2(p.w, p.w); fma2(o2[3][0], pd, v0); fma2(o2[3][1], pd, v1);
        }
    }

    // epilogue: normalize + write bf16 hi/lo splits of attention output
    const int b = bh / H_;
    #pragma unroll
    for (int a = 0; a < 4; a++) {
        int gi = i0 + ty4 + a;
        if (gi >= N_) continue;
        float inv = 1.f / l_[a];
        float2 lo = unpk(o2[a][0]), hi = unpk(o2[a][1]);
        float vals[4] = {lo.x*inv, lo.y*inv, hi.x*inv, hi.y*inv};
        __nv_bfloat16 hb[4], lb[4];
        #pragma unroll
        for (int j = 0; j < 4; j++) {
            hb[j] = __float2bfloat16(vals[j]);
            lb[j] = __float2bfloat16(vals[j] - __bfloat162float(hb[j]));
        }
        size_t off = ((size_t)b * N_ + gi) * D_ + h * DH_ + tx4;
        *(uint2*)(g_ao0 + off) = *(uint2*)hb;
        *(uint2*)(g_ao1 + off) = *(uint2*)lb;
    }
}

// ---------------------------------------------------------------------------
extern "C" void kernel_launch(void* const* d_in, const int* in_sizes, int n_in,
                              void* d_out, int out_size) {
    (void)in_sizes; (void)n_in; (void)out_size;
    const float* x    = (const float*)d_in[0];
    const float* qkvw = (const float*)d_in[1];
    const float* pw   = (const float*)d_in[2];
    const float* pb   = (const float*)d_in[3];
    const float* b1   = (const float*)d_in[4];
    const float* b2   = (const float*)d_in[5];
    const float* b3   = (const float*)d_in[6];
    const int*   map  = (const int*)d_in[7];
    float* out = (float*)d_out;

    const int attn_smem = 4 * 64 * SST * (int)sizeof(float);   // 69,632 B
    cudaFuncSetAttribute(attn_kernel, cudaFuncAttributeMaxDynamicSharedMemorySize, attn_smem);
    cudaFuncSetAttribute(gemm_mma<0>, cudaFuncAttributeMaxDynamicSharedMemorySize, GEMM_SMEM);
    cudaFuncSetAttribute(gemm_mma<1>, cudaFuncAttributeMaxDynamicSharedMemorySize, GEMM_SMEM);

    bias_build<<<CDIV(H_ * BPAD * BPAD, 256), 256>>>(b1, b2, b3, map);
    split_k<0><<<CDIV(MR * D_ / 4, 256), 256>>>(x);
    split_k<1><<<CDIV(3 * D_ * D_ / 4, 256), 256>>>(qkvw);
    split_k<2><<<CDIV(D_ * D_ / 4, 256), 256>>>(pw);

    gemm_mma<0><<<dim3(3 * D_ / 128, CDIV(MR, 128)), 256, GEMM_SMEM>>>(nullptr, nullptr);
    attn_kernel<<<dim3(CDIV(N_, 64), B_ * H_), 256, attn_smem>>>();
    gemm_mma<1><<<dim3(D_ / 128, CDIV(MR, 128)), 256, GEMM_SMEM>>>(pb, out);
}

// round 8
// speedup vs baseline: 2.9172x; 1.3781x over previous
#include <cuda_runtime.h>
#include <cuda_bf16.h>
#include <cstdint>

// ---------------------------------------------------------------------------
// T5RelativeAttention  (B=32, N=577, DIM=768, H=12, Dh=64)
// Round 8: mma.sync bf16x3 GEMMs + flash attention. Fixed the attention smem
// layout: row stride 72 bf16 (144B) for 64-wide tiles (round 6/7 used the
// GEMM's 40 and overflowed shared memory).
// ---------------------------------------------------------------------------

using u64 = unsigned long long;

constexpr int B_   = 32;
constexpr int H_   = 12;
constexpr int N_   = 577;
constexpr int NP_  = 576;
constexpr int D_   = 768;
constexpr int DH_  = 64;
constexpr int NRELC = 2209;
constexpr int BPAD = 640;                 // bias column stride
constexpr int IPADR = 656;                // bias row count (padded)
constexpr int MR   = B_ * N_;             // 18464
constexpr int JP   = 640;                 // padded key dim for Vt

#define CDIV(a,b) (((a)+(b)-1)/(b))

__device__ float g_v[(size_t)B_*H_*N_*DH_];
__device__ float g_bias[(size_t)H_*IPADR*BPAD];
// bf16 hi/lo splits
__device__ __nv_bfloat16 g_x0[(size_t)MR*D_],   g_x1[(size_t)MR*D_];
__device__ __nv_bfloat16 g_w0[(size_t)3*D_*D_], g_w1[(size_t)3*D_*D_];
__device__ __nv_bfloat16 g_p0[(size_t)D_*D_],   g_p1[(size_t)D_*D_];
__device__ __nv_bfloat16 g_ao0[(size_t)MR*D_],  g_ao1[(size_t)MR*D_];
__device__ __nv_bfloat16 g_q0[(size_t)B_*H_*N_*DH_], g_q1[(size_t)B_*H_*N_*DH_];
__device__ __nv_bfloat16 g_k0[(size_t)B_*H_*N_*DH_], g_k1[(size_t)B_*H_*N_*DH_];
__device__ __nv_bfloat16 g_vt0[(size_t)B_*H_*DH_*JP], g_vt1[(size_t)B_*H_*DH_*JP];

// ---------------- mma.sync / cp.async helpers -------------------------------
__device__ __forceinline__ void mma16816(float* d, const uint32_t* a, const uint32_t* b) {
    asm volatile(
        "mma.sync.aligned.m16n8k16.row.col.f32.bf16.bf16.f32 "
        "{%0,%1,%2,%3},{%4,%5,%6,%7},{%8,%9},{%0,%1,%2,%3};"
        : "+f"(d[0]), "+f"(d[1]), "+f"(d[2]), "+f"(d[3])
        : "r"(a[0]), "r"(a[1]), "r"(a[2]), "r"(a[3]), "r"(b[0]), "r"(b[1]));
}
__device__ __forceinline__ uint32_t s2u(const void* p) {
    uint32_t a;
    asm("{ .reg .u64 t; cvta.to.shared.u64 t, %1; cvt.u32.u64 %0, t; }" : "=r"(a) : "l"(p));
    return a;
}
__device__ __forceinline__ void cpa16(uint32_t dst, const void* src, int srcbytes) {
    asm volatile("cp.async.cg.shared.global [%0], [%1], 16, %2;"
                 :: "r"(dst), "l"(src), "r"(srcbytes));
}
__device__ __forceinline__ void cpa_commit() {
    asm volatile("cp.async.commit_group;" ::: "memory");
}
template<int N>
__device__ __forceinline__ void cpa_wait() {
    asm volatile("cp.async.wait_group %0;" :: "n"(N) : "memory");
}
// split-pack: hi = bf16x2(x,y) (x in low half), lo = residual pair
__device__ __forceinline__ void pksplit(float x, float y, uint32_t& hi, uint32_t& lo) {
    __nv_bfloat162 h = __floats2bfloat162_rn(x, y);
    float hx = __bfloat162float(h.x), hy = __bfloat162float(h.y);
    __nv_bfloat162 l = __floats2bfloat162_rn(x - hx, y - hy);
    hi = *(uint32_t*)&h; lo = *(uint32_t*)&l;
}

// ---------------------------------------------------------------------------
// K0: bias table (12 x 656 x 640, zero padded)
// ---------------------------------------------------------------------------
__global__ void bias_build(const float* __restrict__ b1, const float* __restrict__ b2,
                           const float* __restrict__ b3, const int* __restrict__ map) {
    int idx = blockIdx.x * blockDim.x + threadIdx.x;
    constexpr int TOT = H_ * IPADR * BPAD;
    if (idx >= TOT) return;
    int h = idx / (IPADR * BPAD);
    int r = idx - h * (IPADR * BPAD);
    int i = r / BPAD;
    int j = r - i * BPAD;
    float v = 0.f;
    if (i < N_ && j < N_) {
        if (i == NP_)      v = b1[h * N_ + j];
        else if (j == 0)   v = b2[h * NP_ + i];
        else               v = b3[h * NRELC + map[i * NP_ + (j - 1)]];
    }
    g_bias[idx] = v;
}

// ---------------------------------------------------------------------------
// K_split: fp32 -> (hi, lo) bf16.
// ---------------------------------------------------------------------------
template<int SRC>
__global__ void split_k(const float* __restrict__ src) {
    __nv_bfloat16 *hi, *lo; size_t n;
    if (SRC == 0)      { hi = g_x0; lo = g_x1; n = (size_t)MR * D_; }
    else if (SRC == 1) { hi = g_w0; lo = g_w1; n = (size_t)3 * D_ * D_; }
    else               { hi = g_p0; lo = g_p1; n = (size_t)D_ * D_; }
    size_t i = (size_t)blockIdx.x * blockDim.x + threadIdx.x;
    if (i * 4 >= n) return;
    float4 v = *(const float4*)(src + i * 4);
    float vv[4] = {v.x, v.y, v.z, v.w};
    __nv_bfloat16 hb[4], lb[4];
    #pragma unroll
    for (int j = 0; j < 4; j++) {
        hb[j] = __float2bfloat16(vv[j]);
        lb[j] = __float2bfloat16(vv[j] - __bfloat162float(hb[j]));
    }
    *(uint2*)(hi + i * 4) = *(uint2*)hb;
    *(uint2*)(lo + i * 4) = *(uint2*)lb;
}

// ---------------------------------------------------------------------------
// mma.sync GEMM: 128x128 CTA tile, BK=32, 8 warps (2x4), warp tile 64x32.
// (unchanged from round 5 — proven passing)
// ---------------------------------------------------------------------------
constexpr int APAD = 40;                       // bf16 row stride (80B), BK=32 rows
constexpr int MATB = 128 * APAD * 2;           // 10240 bytes per matrix
constexpr int BUFB = 4 * MATB;                 // 40960 bytes per buffer
constexpr int GEMM_SMEM = 2 * BUFB;            // 81920

template<int WHICH>
__global__ void __launch_bounds__(256, 1)
gemm_mma(const float* __restrict__ pbias, float* __restrict__ out) {
    extern __shared__ char sm[];
    const uint32_t sb = s2u(sm);
    const int t = threadIdx.x;
    const int lane = t & 31, wid = t >> 5;
    const int wm = wid >> 2, wn = wid & 3;
    const int m0 = blockIdx.y * 128;
    const int c0 = blockIdx.x * 128;

    const __nv_bfloat16 *A0g, *A1g, *B0g, *B1g;
    if (WHICH == 0) { A0g = g_x0;  A1g = g_x1;  B0g = g_w0; B1g = g_w1; }
    else            { A0g = g_ao0; A1g = g_ao1; B0g = g_p0; B1g = g_p1; }

    const int mrow = t >> 2;
    const int kc   = (t & 3) * 8;
    const bool av0 = (m0 + mrow) < MR;
    const bool av1 = (m0 + mrow + 64) < MR;
    const int arow0 = av0 ? (m0 + mrow) : (MR - 1);
    const int arow1 = av1 ? (m0 + mrow + 64) : (MR - 1);
    const uint32_t soff0 = (uint32_t)(mrow * 80 + kc * 2);
    const uint32_t soff1 = (uint32_t)((mrow + 64) * 80 + kc * 2);

    float acc[4][4][4];
    #pragma unroll
    for (int i = 0; i < 4; i++)
        #pragma unroll
        for (int j = 0; j < 4; j++)
            #pragma unroll
            for (int q = 0; q < 4; q++) acc[i][j][q] = 0.f;

    auto issue = [&](int buf, int kt) {
        const int ko = kt * 32 + kc;
        const uint32_t bs = sb + buf * BUFB;
        size_t a0 = (size_t)arow0 * D_ + ko;
        size_t a1 = (size_t)arow1 * D_ + ko;
        size_t b0 = (size_t)(c0 + mrow) * D_ + ko;
        size_t b1 = (size_t)(c0 + mrow + 64) * D_ + ko;
        cpa16(bs + soff0,            A0g + a0, av0 ? 16 : 0);
        cpa16(bs + soff1,            A0g + a1, av1 ? 16 : 0);
        cpa16(bs + MATB + soff0,     A1g + a0, av0 ? 16 : 0);
        cpa16(bs + MATB + soff1,     A1g + a1, av1 ? 16 : 0);
        cpa16(bs + 2*MATB + soff0,   B0g + b0, 16);
        cpa16(bs + 2*MATB + soff1,   B0g + b1, 16);
        cpa16(bs + 3*MATB + soff0,   B1g + b0, 16);
        cpa16(bs + 3*MATB + soff1,   B1g + b1, 16);
    };

    issue(0, 0);
    cpa_commit();

    const int ar = wm * 64 + (lane >> 2);
    const int br = wn * 32 + (lane >> 2);
    const int fc = (lane & 3) * 2;

    constexpr int NK = 24;
    for (int kt = 0; kt < NK; kt++) {
        const int buf = kt & 1;
        if (kt + 1 < NK) {
            issue(buf ^ 1, kt + 1);
            cpa_commit();
            cpa_wait<1>();
        } else {
            cpa_wait<0>();
        }
        __syncthreads();

        const __nv_bfloat16* sA0 = (const __nv_bfloat16*)(sm + buf * BUFB);
        const __nv_bfloat16* sA1 = (const __nv_bfloat16*)(sm + buf * BUFB + MATB);
        const __nv_bfloat16* sB0 = (const __nv_bfloat16*)(sm + buf * BUFB + 2*MATB);
        const __nv_bfloat16* sB1 = (const __nv_bfloat16*)(sm + buf * BUFB + 3*MATB);

        #pragma unroll
        for (int ks = 0; ks < 2; ks++) {
            const int kb = ks * 16 + fc;
            uint32_t ah[4][4], al[4][4], bh[4][2], bl[4][2];
            #pragma unroll
            for (int am = 0; am < 4; am++) {
                int base = (ar + am * 16) * APAD + kb;
                ah[am][0] = *(const uint32_t*)&sA0[base];
                ah[am][1] = *(const uint32_t*)&sA0[base + 8 * APAD];
                ah[am][2] = *(const uint32_t*)&sA0[base + 8];
                ah[am][3] = *(const uint32_t*)&sA0[base + 8 * APAD + 8];
                al[am][0] = *(const uint32_t*)&sA1[base];
                al[am][1] = *(const uint32_t*)&sA1[base + 8 * APAD];
                al[am][2] = *(const uint32_t*)&sA1[base + 8];
                al[am][3] = *(const uint32_t*)&sA1[base + 8 * APAD + 8];
            }
            #pragma unroll
            for (int an = 0; an < 4; an++) {
                int base = (br + an * 8) * APAD + kb;
                bh[an][0] = *(const uint32_t*)&sB0[base];
                bh[an][1] = *(const uint32_t*)&sB0[base + 8];
                bl[an][0] = *(const uint32_t*)&sB1[base];
                bl[an][1] = *(const uint32_t*)&sB1[base + 8];
            }
            #pragma unroll
            for (int am = 0; am < 4; am++)
                #pragma unroll
                for (int an = 0; an < 4; an++) {
                    mma16816(acc[am][an], ah[am], bh[an]);
                    mma16816(acc[am][an], ah[am], bl[an]);
                    mma16816(acc[am][an], al[am], bh[an]);
                }
        }
        __syncthreads();
    }

    // ---------------- epilogue ----------------------------------------------
    #pragma unroll
    for (int am = 0; am < 4; am++) {
        #pragma unroll
        for (int an = 0; an < 4; an++) {
            int cc = wn * 32 + an * 8 + (lane & 3) * 2;
            #pragma unroll
            for (int rr = 0; rr < 2; rr++) {
                int r = m0 + wm * 64 + am * 16 + (lane >> 2) + rr * 8;
                if (r >= MR) continue;
                float vx = acc[am][an][rr*2], vy = acc[am][an][rr*2+1];
                if (WHICH == 0) {
                    const int s  = c0 / D_;
                    const int w  = (c0 - s * D_) + cc;
                    const int hh = w >> 6, d = w & 63;
                    int bb = r / N_, n = r - bb * N_;
                    size_t off = (((size_t)(bb * H_ + hh)) * N_ + n) * DH_ + d;
                    if (s == 2) {
                        *(float2*)(g_v + off) = make_float2(vx, vy);
                    } else {
                        if (s == 0) { vx *= 0.125f; vy *= 0.125f; }
                        uint32_t hi, lo;
                        pksplit(vx, vy, hi, lo);
                        __nv_bfloat16* dh = (s == 0) ? g_q0 : g_k0;
                        __nv_bfloat16* dl = (s == 0) ? g_q1 : g_k1;
                        *(uint32_t*)(dh + off) = hi;
                        *(uint32_t*)(dl + off) = lo;
                    }
                } else {
                    float2 bv = *(const float2*)(pbias + c0 + cc);
                    *(float2*)(out + (size_t)r * D_ + c0 + cc) =
                        make_float2(vx + bv.x, vy + bv.y);
                }
            }
        }
    }
}

// ---------------------------------------------------------------------------
// V transpose: g_v [bh][j][d] fp32 -> g_vt0/1 [bh][d][JP] bf16 hi/lo.
// ---------------------------------------------------------------------------
__global__ void __launch_bounds__(256) vtrans() {
    __shared__ float ts[64][65];
    const int bh = blockIdx.y;
    const int j0 = blockIdx.x * 64;
    const int t  = threadIdx.x;
    const int d  = t & 63, jb = t >> 6;
    #pragma unroll
    for (int i = 0; i < 16; i++) {
        int j = jb * 16 + i;
        int gj = j0 + j;
        ts[j][d] = (gj < N_) ? g_v[((size_t)bh * N_ + gj) * DH_ + d] : 0.f;
    }
    __syncthreads();
    const int jp = t & 31, db = t >> 5;
    #pragma unroll
    for (int i = 0; i < 8; i++) {
        int d2 = db * 8 + i;
        float x0 = ts[2*jp][d2], x1 = ts[2*jp+1][d2];
        uint32_t hi, lo;
        pksplit(x0, x1, hi, lo);
        size_t off = ((size_t)bh * DH_ + d2) * JP + j0 + 2 * jp;
        *(uint32_t*)(g_vt0 + off) = hi;
        *(uint32_t*)(g_vt1 + off) = lo;
    }
}

// ---------------------------------------------------------------------------
// K2: tensor-core flash attention. 128 threads = 4 warps, warp owns 16 q-rows.
// smem: rows of 64 bf16 + 8 pad = 72 elems (144B).
//   Qh @0, Ql @9216; KV buf b @18432+b*36864: Kh +0, Kl +9216, Vh +18432, Vl +27648
// ---------------------------------------------------------------------------
constexpr int ATP   = 72;                      // bf16 row stride (144B)
constexpr int AMTB  = 64 * ATP * 2;            // 9216 bytes per matrix
constexpr int AKVB  = 4 * AMTB;                // 36864 per KV buffer
constexpr int ATT_SMEM = 2 * AMTB + 2 * AKVB;  // 92160

__global__ void __launch_bounds__(128, 1) attn_mma() {
    extern __shared__ char sm[];
    const uint32_t sb = s2u(sm);
    const int t = threadIdx.x, lane = t & 31, wid = t >> 5;
    const int gid = lane >> 2, tg = lane & 3;
    const int bh = blockIdx.y, h = bh % H_, b = bh / H_;
    const int i0 = blockIdx.x * 64;

    const size_t kvbase = (size_t)bh * N_ * DH_;
    const size_t vtbase = (size_t)bh * DH_ * JP;

    const int lrow = t >> 1;                   // 0..63
    const int lkc  = (t & 1) * 32;             // element offset in row

    // Q load (once)
    {
        bool v = (i0 + lrow) < N_;
        int qrow = v ? (i0 + lrow) : (N_ - 1);
        size_t g = kvbase + (size_t)qrow * DH_ + lkc;
        uint32_t s0 = sb + lrow * 144 + lkc * 2;
        #pragma unroll
        for (int i = 0; i < 4; i++) {
            cpa16(s0 + i * 16,        g_q0 + g + i * 8, v ? 16 : 0);
            cpa16(s0 + AMTB + i * 16, g_q1 + g + i * 8, v ? 16 : 0);
        }
    }
    cpa_commit();

    auto issueKV = [&](int buf, int jt) {
        int j0 = jt * 64;
        bool v = (j0 + lrow) < N_;
        int krow = v ? (j0 + lrow) : (N_ - 1);
        size_t gk = kvbase + (size_t)krow * DH_ + lkc;
        size_t gv = vtbase + (size_t)lrow * JP + j0 + lkc;
        uint32_t s0 = sb + 2 * AMTB + buf * AKVB + lrow * 144 + lkc * 2;
        #pragma unroll
        for (int i = 0; i < 4; i++) {
            cpa16(s0 + i * 16,            g_k0  + gk + i * 8, v ? 16 : 0);
            cpa16(s0 + AMTB + i * 16,     g_k1  + gk + i * 8, v ? 16 : 0);
            cpa16(s0 + 2 * AMTB + i * 16, g_vt0 + gv + i * 8, 16);
            cpa16(s0 + 3 * AMTB + i * 16, g_vt1 + gv + i * 8, 16);
        }
    };
    issueKV(0, 0);
    cpa_commit();

    const int war = wid * 16 + gid;            // local q row (0..63)
    float m0r = -1e30f, m1r = -1e30f, l0 = 0.f, l1 = 0.f;
    float o[8][4];
    #pragma unroll
    for (int a = 0; a < 8; a++)
        #pragma unroll
        for (int q = 0; q < 4; q++) o[a][q] = 0.f;

    const __nv_bfloat16* SQh = (const __nv_bfloat16*)sm;
    const __nv_bfloat16* SQl = SQh + 64 * ATP;

    for (int kt = 0; kt < 10; kt++) {
        const int buf = kt & 1;
        if (kt < 9) { issueKV(buf ^ 1, kt + 1); cpa_commit(); cpa_wait<1>(); }
        else        { cpa_wait<0>(); }
        __syncthreads();

        const int j0 = kt * 64;
        const __nv_bfloat16* SKh = (const __nv_bfloat16*)(sm + 2 * AMTB + buf * AKVB);
        const __nv_bfloat16* SKl = SKh + 64 * ATP;
        const __nv_bfloat16* SVh = SKh + 2 * 64 * ATP;
        const __nv_bfloat16* SVl = SKh + 3 * 64 * ATP;

        // bias fragments (rows padded to IPADR=656 so i0+war+8 <= 647 is safe)
        float2 bfr[8][2];
        {
            size_t r0 = ((size_t)h * IPADR + i0 + war) * BPAD + j0 + tg * 2;
            size_t r1 = r0 + 8 * BPAD;
            #pragma unroll
            for (int a = 0; a < 8; a++) {
                bfr[a][0] = *(const float2*)(g_bias + r0 + a * 8);
                bfr[a][1] = *(const float2*)(g_bias + r1 + a * 8);
            }
        }

        // S = Q K^T (bf16x3)
        float s[8][4];
        #pragma unroll
        for (int a = 0; a < 8; a++)
            #pragma unroll
            for (int q = 0; q < 4; q++) s[a][q] = 0.f;

        #pragma unroll
        for (int t4 = 0; t4 < 4; t4++) {
            const int kb = t4 * 16 + tg * 2;
            uint32_t qh[4], ql[4];
            int ab = war * ATP + kb;
            qh[0] = *(const uint32_t*)&SQh[ab];
            qh[1] = *(const uint32_t*)&SQh[ab + 8 * ATP];
            qh[2] = *(const uint32_t*)&SQh[ab + 8];
            qh[3] = *(const uint32_t*)&SQh[ab + 8 * ATP + 8];
            ql[0] = *(const uint32_t*)&SQl[ab];
            ql[1] = *(const uint32_t*)&SQl[ab + 8 * ATP];
            ql[2] = *(const uint32_t*)&SQl[ab + 8];
            ql[3] = *(const uint32_t*)&SQl[ab + 8 * ATP + 8];
            #pragma unroll
            for (int a = 0; a < 8; a++) {
                int bb = (a * 8 + gid) * ATP + kb;
                uint32_t kh[2] = {*(const uint32_t*)&SKh[bb], *(const uint32_t*)&SKh[bb + 8]};
                uint32_t kl[2] = {*(const uint32_t*)&SKl[bb], *(const uint32_t*)&SKl[bb + 8]};
                mma16816(s[a], qh, kh);
                mma16816(s[a], qh, kl);
                mma16816(s[a], ql, kh);
            }
        }

        // + bias, mask invalid keys (only last tile)
        #pragma unroll
        for (int a = 0; a < 8; a++) {
            s[a][0] += bfr[a][0].x; s[a][1] += bfr[a][0].y;
            s[a][2] += bfr[a][1].x; s[a][3] += bfr[a][1].y;
        }
        if (j0 + 64 > N_) {
            #pragma unroll
            for (int a = 0; a < 8; a++) {
                int jc = j0 + a * 8 + tg * 2;
                if (jc >= N_)     { s[a][0] = -1e30f; s[a][2] = -1e30f; }
                if (jc + 1 >= N_) { s[a][1] = -1e30f; s[a][3] = -1e30f; }
            }
        }

        // online softmax (rows r and r+8)
        float mx0 = -1e30f, mx1 = -1e30f;
        #pragma unroll
        for (int a = 0; a < 8; a++) {
            mx0 = fmaxf(mx0, fmaxf(s[a][0], s[a][1]));
            mx1 = fmaxf(mx1, fmaxf(s[a][2], s[a][3]));
        }
        mx0 = fmaxf(mx0, __shfl_xor_sync(0xffffffffu, mx0, 1));
        mx0 = fmaxf(mx0, __shfl_xor_sync(0xffffffffu, mx0, 2));
        mx1 = fmaxf(mx1, __shfl_xor_sync(0xffffffffu, mx1, 1));
        mx1 = fmaxf(mx1, __shfl_xor_sync(0xffffffffu, mx1, 2));
        float mn0 = fmaxf(m0r, mx0), mn1 = fmaxf(m1r, mx1);
        float c0f = __expf(m0r - mn0), c1f = __expf(m1r - mn1);
        m0r = mn0; m1r = mn1;
        float rs0 = 0.f, rs1 = 0.f;
        #pragma unroll
        for (int a = 0; a < 8; a++) {
            s[a][0] = __expf(s[a][0] - mn0);
            s[a][1] = __expf(s[a][1] - mn0);
            s[a][2] = __expf(s[a][2] - mn1);
            s[a][3] = __expf(s[a][3] - mn1);
            rs0 += s[a][0] + s[a][1];
            rs1 += s[a][2] + s[a][3];
        }
        rs0 += __shfl_xor_sync(0xffffffffu, rs0, 1);
        rs0 += __shfl_xor_sync(0xffffffffu, rs0, 2);
        rs1 += __shfl_xor_sync(0xffffffffu, rs1, 1);
        rs1 += __shfl_xor_sync(0xffffffffu, rs1, 2);
        l0 = l0 * c0f + rs0;
        l1 = l1 * c1f + rs1;
        #pragma unroll
        for (int a = 0; a < 8; a++) {
            o[a][0] *= c0f; o[a][1] *= c0f;
            o[a][2] *= c1f; o[a][3] *= c1f;
        }

        // O += P V  (P repacked reg->reg into A-frags, bf16x3)
        #pragma unroll
        for (int t4 = 0; t4 < 4; t4++) {
            uint32_t ah[4], al[4];
            pksplit(s[2*t4][0],   s[2*t4][1],   ah[0], al[0]);
            pksplit(s[2*t4][2],   s[2*t4][3],   ah[1], al[1]);
            pksplit(s[2*t4+1][0], s[2*t4+1][1], ah[2], al[2]);
            pksplit(s[2*t4+1][2], s[2*t4+1][3], ah[3], al[3]);
            const int kb = t4 * 16 + tg * 2;
            #pragma unroll
            for (int a = 0; a < 8; a++) {
                int bb = (a * 8 + gid) * ATP + kb;
                uint32_t vh[2] = {*(const uint32_t*)&SVh[bb], *(const uint32_t*)&SVh[bb + 8]};
                uint32_t vl[2] = {*(const uint32_t*)&SVl[bb], *(const uint32_t*)&SVl[bb + 8]};
                mma16816(o[a], ah, vh);
                mma16816(o[a], ah, vl);
                mma16816(o[a], al, vh);
            }
        }
        __syncthreads();
    }

    // epilogue: normalize + write bf16 hi/lo splits for proj GEMM
    const float inv0 = 1.f / l0, inv1 = 1.f / l1;
    const int gi0 = i0 + war, gi1 = gi0 + 8;
    const size_t ro0 = ((size_t)b * N_ + gi0) * D_ + h * DH_;
    const size_t ro1 = ((size_t)b * N_ + gi1) * D_ + h * DH_;
    #pragma unroll
    for (int a = 0; a < 8; a++) {
        int d = a * 8 + tg * 2;
        if (gi0 < N_) {
            uint32_t hi, lo;
            pksplit(o[a][0] * inv0, o[a][1] * inv0, hi, lo);
            *(uint32_t*)(g_ao0 + ro0 + d) = hi;
            *(uint32_t*)(g_ao1 + ro0 + d) = lo;
        }
        if (gi1 < N_) {
            uint32_t hi, lo;
            pksplit(o[a][2] * inv1, o[a][3] * inv1, hi, lo);
            *(uint32_t*)(g_ao0 + ro1 + d) = hi;
            *(uint32_t*)(g_ao1 + ro1 + d) = lo;
        }
    }
}

// ---------------------------------------------------------------------------
extern "C" void kernel_launch(void* const* d_in, const int* in_sizes, int n_in,
                              void* d_out, int out_size) {
    (void)in_sizes; (void)n_in; (void)out_size;
    const float* x    = (const float*)d_in[0];
    const float* qkvw = (const float*)d_in[1];
    const float* pw   = (const float*)d_in[2];
    const float* pb   = (const float*)d_in[3];
    const float* b1   = (const float*)d_in[4];
    const float* b2   = (const float*)d_in[5];
    const float* b3   = (const float*)d_in[6];
    const int*   map  = (const int*)d_in[7];
    float* out = (float*)d_out;

    cudaFuncSetAttribute(attn_mma, cudaFuncAttributeMaxDynamicSharedMemorySize, ATT_SMEM);
    cudaFuncSetAttribute(gemm_mma<0>, cudaFuncAttributeMaxDynamicSharedMemorySize, GEMM_SMEM);
    cudaFuncSetAttribute(gemm_mma<1>, cudaFuncAttributeMaxDynamicSharedMemorySize, GEMM_SMEM);

    bias_build<<<CDIV(H_ * IPADR * BPAD, 256), 256>>>(b1, b2, b3, map);
    split_k<0><<<CDIV(MR * D_ / 4, 256), 256>>>(x);
    split_k<1><<<CDIV(3 * D_ * D_ / 4, 256), 256>>>(qkvw);
    split_k<2><<<CDIV(D_ * D_ / 4, 256), 256>>>(pw);

    gemm_mma<0><<<dim3(3 * D_ / 128, CDIV(MR, 128)), 256, GEMM_SMEM>>>(nullptr, nullptr);
    vtrans<<<dim3(JP / 64, B_ * H_), 256>>>();
    attn_mma<<<dim3(CDIV(N_, 64), B_ * H_), 128, ATT_SMEM>>>();
    gemm_mma<1><<<dim3(D_ / 128, CDIV(MR, 128)), 256, GEMM_SMEM>>>(pb, out);
}